// round 9
// baseline (speedup 1.0000x reference)
#include <cuda_runtime.h>
#include <cuda_bf16.h>
#include <cstdint>

// Problem constants
#define BSZ   2
#define TSEQ  2048
#define DMODEL 1024
#define NHEAD 16
#define HDIM  64
#define INNER 1024
#define E3    3072
#define MROWS (BSZ*TSEQ)    // 4096
#define KDIM  1024

#define QKV_ELEMS ((size_t)BSZ*NHEAD*TSEQ*HDIM)   // 4M

// Split-bf16 scratch (hi + lo arrays)
__device__ __align__(256) __nv_bfloat16 g_xH[(size_t)MROWS*KDIM];
__device__ __align__(256) __nv_bfloat16 g_xL[(size_t)MROWS*KDIM];
__device__ __align__(256) __nv_bfloat16 g_w1H[(size_t)E3*KDIM];
__device__ __align__(256) __nv_bfloat16 g_w1L[(size_t)E3*KDIM];
__device__ __align__(256) __nv_bfloat16 g_w2H[(size_t)DMODEL*INNER];
__device__ __align__(256) __nv_bfloat16 g_w2L[(size_t)DMODEL*INNER];
__device__ __align__(256) __nv_bfloat16 g_QH[QKV_ELEMS];
__device__ __align__(256) __nv_bfloat16 g_QL[QKV_ELEMS];
__device__ __align__(256) __nv_bfloat16 g_KH[QKV_ELEMS];
__device__ __align__(256) __nv_bfloat16 g_KL[QKV_ELEMS];
__device__ __align__(256) __nv_bfloat16 g_VH[QKV_ELEMS];
__device__ __align__(256) __nv_bfloat16 g_VL[QKV_ELEMS];
__device__ __align__(256) __nv_bfloat16 g_ATTH[(size_t)MROWS*INNER];
__device__ __align__(256) __nv_bfloat16 g_ATTL[(size_t)MROWS*INNER];

// ===========================================================================
// Helpers
// ===========================================================================
__device__ __forceinline__ uint32_t smem_u32(const void* p) {
    uint32_t a;
    asm("{ .reg .u64 t; cvta.to.shared.u64 t, %1; cvt.u32.u64 %0, t; }"
        : "=r"(a) : "l"(p));
    return a;
}
__device__ __forceinline__ void ldsm_x4(uint32_t& r0, uint32_t& r1,
                                        uint32_t& r2, uint32_t& r3, uint32_t a) {
    asm volatile("ldmatrix.sync.aligned.m8n8.x4.shared.b16 {%0,%1,%2,%3}, [%4];"
                 : "=r"(r0), "=r"(r1), "=r"(r2), "=r"(r3) : "r"(a));
}
__device__ __forceinline__ void ldsm_x4_t(uint32_t& r0, uint32_t& r1,
                                          uint32_t& r2, uint32_t& r3, uint32_t a) {
    asm volatile("ldmatrix.sync.aligned.m8n8.x4.trans.shared.b16 {%0,%1,%2,%3}, [%4];"
                 : "=r"(r0), "=r"(r1), "=r"(r2), "=r"(r3) : "r"(a));
}
__device__ __forceinline__ void mma_bf16(float* d, const uint32_t* a,
                                         uint32_t b0, uint32_t b1) {
    asm volatile(
        "mma.sync.aligned.m16n8k16.row.col.f32.bf16.bf16.f32 "
        "{%0,%1,%2,%3}, {%4,%5,%6,%7}, {%8,%9}, {%0,%1,%2,%3};"
        : "+f"(d[0]), "+f"(d[1]), "+f"(d[2]), "+f"(d[3])
        : "r"(a[0]), "r"(a[1]), "r"(a[2]), "r"(a[3]), "r"(b0), "r"(b1));
}
__device__ __forceinline__ float ex2f(float x) {
    float r;
    asm("ex2.approx.f32 %0, %1;" : "=f"(r) : "f"(x));
    return r;
}
__device__ __forceinline__ void split2(float a, float b, uint32_t& hi, uint32_t& lo) {
    __nv_bfloat162 h = __floats2bfloat162_rn(a, b);
    hi = *reinterpret_cast<uint32_t*>(&h);
    __nv_bfloat162 l = __floats2bfloat162_rn(a - __bfloat162float(h.x),
                                             b - __bfloat162float(h.y));
    lo = *reinterpret_cast<uint32_t*>(&l);
}
__device__ __forceinline__ void cvt_split4(float4 v, uint2& hi, uint2& lo) {
    split2(v.x, v.y, hi.x, lo.x);
    split2(v.z, v.w, hi.y, lo.y);
}
#define CP_ASYNC16(dst, src) \
    asm volatile("cp.async.cg.shared.global [%0], [%1], 16;" :: \
                 "r"(dst), "l"(src) : "memory")
#define CP_COMMIT() asm volatile("cp.async.commit_group;" ::: "memory")
#define CP_WAIT(N)  asm volatile("cp.async.wait_group %0;" :: "n"(N) : "memory")

// ===========================================================================
// Prep: fp32 -> split bf16 (hi, lo)
// ===========================================================================
__global__ __launch_bounds__(256) void split_kernel(
    const float* __restrict__ src, __nv_bfloat16* __restrict__ hi,
    __nv_bfloat16* __restrict__ lo, int n4)
{
    int i = blockIdx.x * 256 + threadIdx.x;
    if (i < n4) {
        float4 v = reinterpret_cast<const float4*>(src)[i];
        uint2 h, l;
        cvt_split4(v, h, l);
        reinterpret_cast<uint2*>(hi)[i] = h;
        reinterpret_cast<uint2*>(lo)[i] = l;
    }
}

// ===========================================================================
// Split-bf16 tensor-core GEMM.
// 256 threads (8 warps, 4x2), CTA tile 128x128, warp tile 32x64.
// K-chunk 32, 3-stage cp.async ring, lookahead 2 (CP_WAIT(2)).
// mode 0: scatter + re-split into g_{Q,K,V}{H,L} ([b][h][t][d])
// mode 1: write fp32 C[m*DMODEL+n] + bias
// ===========================================================================
#define GST 40960u                    // bytes/stage: 4 arrays x 128 rows x 80B
#define GSTAGES 3
#define GEMM_SMEM (GSTAGES*GST)       // 122880
#define GNCH (KDIM/32)                // 32 chunks

__global__ __launch_bounds__(256) void gemm_bf16_kernel(
    const __nv_bfloat16* __restrict__ Ah, const __nv_bfloat16* __restrict__ Al,
    const __nv_bfloat16* __restrict__ Bh, const __nv_bfloat16* __restrict__ Bl,
    const float* __restrict__ bias, float* __restrict__ C, int mode)
{
    extern __shared__ char smem[];
    const uint32_t sb = smem_u32(smem);
    const int tid  = threadIdx.x;
    const int lane = tid & 31;
    const int warp = tid >> 5;        // 0..7
    const int wm = warp & 3;          // m: 32*wm
    const int wn = warp >> 2;         // n: 64*wn
    const int n0 = blockIdx.x * 128;
    const int m0 = blockIdx.y * 128;

    // copy role: arr 0=Ah 1=Al 2=Bh 3=Bl ; 64 threads per array, 2 rows each
    const int cp_arr = tid >> 6;
    const int cp_r0  = (tid & 63) * 2;
    const __nv_bfloat16* srcp =
        (cp_arr == 0) ? Ah : (cp_arr == 1) ? Al : (cp_arr == 2) ? Bh : Bl;
    srcp += (size_t)((cp_arr < 2 ? m0 : n0) + cp_r0) * KDIM;
    const uint32_t dst0 = sb + (uint32_t)cp_arr * 10240u + (uint32_t)cp_r0 * 80u;

    auto issue_chunk = [&](int ch, int stage) {
        uint32_t d = dst0 + (uint32_t)stage * GST;
        const __nv_bfloat16* s = srcp + ch * 32;
#pragma unroll
        for (int rr = 0; rr < 2; rr++) {
#pragma unroll
            for (int c = 0; c < 4; c++)
                CP_ASYNC16(d + rr * 80u + c * 16u, s + (size_t)rr * KDIM + c * 8);
        }
        CP_COMMIT();
    };

    float acc[2][8][4];
#pragma unroll
    for (int i = 0; i < 2; i++)
#pragma unroll
        for (int f = 0; f < 8; f++)
#pragma unroll
            for (int q = 0; q < 4; q++) acc[i][f][q] = 0.f;

    const int aRowB = wm * 32 + (lane & 15);
    const int aColB = (lane >> 4) * 8;
    const int bRowB = wn * 64 + ((lane >> 4) * 8) + (lane & 7);
    const int bColB = ((lane >> 3) & 1) * 8;

    issue_chunk(0, 0);
    issue_chunk(1, 1);

    for (int ch = 0; ch < GNCH; ch++) {
        const int st = ch % GSTAGES;
        if (ch + 2 < GNCH) {
            issue_chunk(ch + 2, (ch + 2) % GSTAGES);
            CP_WAIT(2);
        } else if (ch + 1 < GNCH) {
            CP_WAIT(1);
        } else {
            CP_WAIT(0);
        }
        __syncthreads();

        const uint32_t base = sb + (uint32_t)st * GST;
        const uint32_t bAH = base, bAL = base + 10240u;
        const uint32_t bBH = base + 20480u, bBL = base + 30720u;

#pragma unroll
        for (int ks = 0; ks < 32; ks += 16) {
            uint32_t ah[2][4], bh[4][4], bl[4][4];
#pragma unroll
            for (int i = 0; i < 2; i++) {
                uint32_t eo = (uint32_t)((aRowB + i * 16) * 80 + (ks + aColB) * 2);
                ldsm_x4(ah[i][0], ah[i][1], ah[i][2], ah[i][3], bAH + eo);
            }
#pragma unroll
            for (int j = 0; j < 4; j++) {
                uint32_t eo = (uint32_t)((bRowB + j * 16) * 80 + (ks + bColB) * 2);
                ldsm_x4(bh[j][0], bh[j][1], bh[j][2], bh[j][3], bBH + eo);
            }
#pragma unroll
            for (int j = 0; j < 4; j++) {
                uint32_t eo = (uint32_t)((bRowB + j * 16) * 80 + (ks + bColB) * 2);
                ldsm_x4(bl[j][0], bl[j][1], bl[j][2], bl[j][3], bBL + eo);
            }
#pragma unroll
            for (int i = 0; i < 2; i++)
#pragma unroll
                for (int j = 0; j < 4; j++) {
                    mma_bf16(acc[i][j * 2 + 0], ah[i], bh[j][0], bh[j][1]);
                    mma_bf16(acc[i][j * 2 + 1], ah[i], bh[j][2], bh[j][3]);
                    mma_bf16(acc[i][j * 2 + 0], ah[i], bl[j][0], bl[j][1]);
                    mma_bf16(acc[i][j * 2 + 1], ah[i], bl[j][2], bl[j][3]);
                }
#pragma unroll
            for (int i = 0; i < 2; i++) {
                uint32_t eo = (uint32_t)((aRowB + i * 16) * 80 + (ks + aColB) * 2);
                ldsm_x4(ah[i][0], ah[i][1], ah[i][2], ah[i][3], bAL + eo);
            }
#pragma unroll
            for (int i = 0; i < 2; i++)
#pragma unroll
                for (int j = 0; j < 4; j++) {
                    mma_bf16(acc[i][j * 2 + 0], ah[i], bh[j][0], bh[j][1]);
                    mma_bf16(acc[i][j * 2 + 1], ah[i], bh[j][2], bh[j][3]);
                }
        }
        __syncthreads();
    }

    // Epilogue
#pragma unroll
    for (int i = 0; i < 2; i++) {
#pragma unroll
        for (int f = 0; f < 8; f++) {
            int row = m0 + wm * 32 + i * 16 + (lane >> 2);
            int col = n0 + wn * 64 + f * 8 + (lane & 3) * 2;
            float b0 = bias[col], b1 = bias[col + 1];
            float p00 = acc[i][f][0] + b0, p01 = acc[i][f][1] + b1;
            float p10 = acc[i][f][2] + b0, p11 = acc[i][f][3] + b1;
            if (mode == 0) {
                int which = col >> 10, h = (col >> 6) & (NHEAD - 1), d = col & (HDIM - 1);
                __nv_bfloat16* dh = (which == 0) ? g_QH : (which == 1) ? g_KH : g_VH;
                __nv_bfloat16* dl = (which == 0) ? g_QL : (which == 1) ? g_KL : g_VL;
#pragma unroll
                for (int rr = 0; rr < 2; rr++) {
                    int r = row + rr * 8;
                    int bb = r >> 11, tt = r & (TSEQ - 1);
                    size_t idx = (((size_t)(bb * NHEAD + h)) * TSEQ + tt) * HDIM + d;
                    uint32_t hv, lv;
                    split2(rr ? p10 : p00, rr ? p11 : p01, hv, lv);
                    *reinterpret_cast<uint32_t*>(dh + idx) = hv;
                    *reinterpret_cast<uint32_t*>(dl + idx) = lv;
                }
            } else {
                float2 v0 = {p00, p01}, v1 = {p10, p11};
                *reinterpret_cast<float2*>(&C[(size_t)row * DMODEL + col]) = v0;
                *reinterpret_cast<float2*>(&C[(size_t)(row + 8) * DMODEL + col]) = v1;
            }
        }
    }
}

// ===========================================================================
// Tensor-core flash attention, split-bf16 inputs, anti-causal (keep j >= i).
// 256 threads, 8 warps x 16 query rows, key tiles of 64, cp.async KV pipeline.
// (unchanged from round 5 — passed)
// ===========================================================================
#define LKV 72
#define AQH 0
#define AQL (128*LKV*2)               // 18432
#define AKV0 (2*128*LKV*2)            // 36864
#define KVST (4*64*LKV*2)             // 36864 per stage (KH,KL,VH,VL)
#define ATT2_SMEM (AKV0 + 2*KVST)     // 110592

__global__ __launch_bounds__(256) void attn_mma_kernel()
{
    extern __shared__ char smem[];
    const uint32_t sb = smem_u32(smem);
    const int tid  = threadIdx.x;
    const int lane = tid & 31;
    const int warp = tid >> 5;
    const int q0 = blockIdx.x * 128;
    const int h  = blockIdx.y;
    const int b  = blockIdx.z;
    const size_t head_off = (size_t)(b * NHEAD + h) * TSEQ * HDIM;

    const float QSCALE = 0.18033688011112042f;   // 0.125 * log2(e)

    auto issue_kv = [&](int stage, int j0) {
        uint32_t kvb = sb + AKV0 + (uint32_t)stage * KVST;
#pragma unroll
        for (int it = 0; it < 8; it++) {
            int idx = tid + it * 256;
            int arr = idx >> 9;
            int rem = idx & 511;
            int r = rem >> 3, c8 = rem & 7;
            const __nv_bfloat16* s =
                (arr == 0) ? g_KH : (arr == 1) ? g_KL : (arr == 2) ? g_VH : g_VL;
            s += head_off + (size_t)(j0 + r) * HDIM + c8 * 8;
            uint32_t d = kvb + (uint32_t)arr * 9216u + (uint32_t)(r * 144 + c8 * 16);
            CP_ASYNC16(d, s);
        }
        CP_COMMIT();
    };
    issue_kv(0, q0);

#pragma unroll
    for (int it = 0; it < 4; it++) {
        int idx = tid + it * 256;
        int r = idx >> 3, c8 = idx & 7;
        size_t goff = head_off + (size_t)(q0 + r) * HDIM + c8 * 8;
        uint32_t soff = (uint32_t)(r * 144 + c8 * 16);
        *reinterpret_cast<uint4*>(smem + AQH + soff) =
            *reinterpret_cast<const uint4*>(g_QH + goff);
        *reinterpret_cast<uint4*>(smem + AQL + soff) =
            *reinterpret_cast<const uint4*>(g_QL + goff);
    }
    __syncthreads();

    uint32_t qh[4][4], ql[4][4];
    {
        const int aRow = warp * 16 + (lane & 15);
        const int aCol = (lane >> 4) * 8;
#pragma unroll
        for (int kt = 0; kt < 4; kt++) {
            uint32_t eo = (uint32_t)(aRow * LKV + kt * 16 + aCol) * 2u;
            ldsm_x4(qh[kt][0], qh[kt][1], qh[kt][2], qh[kt][3], sb + AQH + eo);
            ldsm_x4(ql[kt][0], ql[kt][1], ql[kt][2], ql[kt][3], sb + AQL + eo);
        }
    }

    float accO[8][4];
#pragma unroll
    for (int n = 0; n < 8; n++)
#pragma unroll
        for (int c = 0; c < 4; c++) accO[n][c] = 0.f;
    float mrow[2] = {-1e30f, -1e30f};
    float lrow[2] = {0.f, 0.f};

    const int ntiles = (TSEQ - q0) / 64;

    for (int tc = 0; tc < ntiles; tc++) {
        const int j0 = q0 + tc * 64;
        const int st = tc & 1;
        if (tc + 1 < ntiles) {
            issue_kv(st ^ 1, j0 + 64);
            CP_WAIT(1);
        } else {
            CP_WAIT(0);
        }
        __syncthreads();

        const uint32_t kvb = sb + AKV0 + (uint32_t)st * KVST;
        const uint32_t bKH = kvb, bKL = kvb + 9216u;
        const uint32_t bVH = kvb + 18432u, bVL = kvb + 27648u;

        float accS[8][4];
#pragma unroll
        for (int n = 0; n < 8; n++)
#pragma unroll
            for (int c = 0; c < 4; c++) accS[n][c] = 0.f;

        const int kRow = ((lane >> 4) * 8) + (lane & 7);
        const int kCol = ((lane >> 3) & 1) * 8;
#pragma unroll
        for (int kt = 0; kt < 4; kt++) {
#pragma unroll
            for (int j2 = 0; j2 < 4; j2++) {
                uint32_t eo = (uint32_t)((j2 * 16 + kRow) * LKV + kt * 16 + kCol) * 2u;
                uint32_t kh0, kh1, kh2, kh3, kl0, kl1, kl2, kl3;
                ldsm_x4(kh0, kh1, kh2, kh3, bKH + eo);
                mma_bf16(accS[j2 * 2 + 0], qh[kt], kh0, kh1);
                mma_bf16(accS[j2 * 2 + 1], qh[kt], kh2, kh3);
                mma_bf16(accS[j2 * 2 + 0], ql[kt], kh0, kh1);
                mma_bf16(accS[j2 * 2 + 1], ql[kt], kh2, kh3);
                ldsm_x4(kl0, kl1, kl2, kl3, bKL + eo);
                mma_bf16(accS[j2 * 2 + 0], qh[kt], kl0, kl1);
                mma_bf16(accS[j2 * 2 + 1], qh[kt], kl2, kl3);
            }
        }

#pragma unroll
        for (int n = 0; n < 8; n++)
#pragma unroll
            for (int c = 0; c < 4; c++) accS[n][c] *= QSCALE;

        if (j0 - q0 < 128) {
            int rq = q0 + warp * 16 + (lane >> 2);
#pragma unroll
            for (int nt = 0; nt < 8; nt++) {
                int cb = j0 + nt * 8 + 2 * (lane & 3);
                if (cb     < rq)     accS[nt][0] = -1e30f;
                if (cb + 1 < rq)     accS[nt][1] = -1e30f;
                if (cb     < rq + 8) accS[nt][2] = -1e30f;
                if (cb + 1 < rq + 8) accS[nt][3] = -1e30f;
            }
        }

#pragma unroll
        for (int r = 0; r < 2; r++) {
            float tm = -1e30f;
#pragma unroll
            for (int nt = 0; nt < 8; nt++)
                tm = fmaxf(tm, fmaxf(accS[nt][r * 2], accS[nt][r * 2 + 1]));
            tm = fmaxf(tm, __shfl_xor_sync(0xffffffffu, tm, 1));
            tm = fmaxf(tm, __shfl_xor_sync(0xffffffffu, tm, 2));
            float mnew = fmaxf(mrow[r], tm);
            float alpha = ex2f(mrow[r] - mnew);
            mrow[r] = mnew;
            float rs = 0.f;
#pragma unroll
            for (int nt = 0; nt < 8; nt++) {
                float p0 = ex2f(accS[nt][r * 2]     - mnew);
                float p1 = ex2f(accS[nt][r * 2 + 1] - mnew);
                accS[nt][r * 2] = p0;
                accS[nt][r * 2 + 1] = p1;
                rs += p0 + p1;
            }
            rs += __shfl_xor_sync(0xffffffffu, rs, 1);
            rs += __shfl_xor_sync(0xffffffffu, rs, 2);
            lrow[r] = lrow[r] * alpha + rs;
#pragma unroll
            for (int nt = 0; nt < 8; nt++) {
                accO[nt][r * 2]     *= alpha;
                accO[nt][r * 2 + 1] *= alpha;
            }
        }

        const int vRow = lane & 15;
        const int vCol = (lane >> 4) * 8;
#pragma unroll
        for (int kt = 0; kt < 4; kt++) {
            uint32_t pah[4], pal[4];
            split2(accS[2 * kt][0],     accS[2 * kt][1],     pah[0], pal[0]);
            split2(accS[2 * kt][2],     accS[2 * kt][3],     pah[1], pal[1]);
            split2(accS[2 * kt + 1][0], accS[2 * kt + 1][1], pah[2], pal[2]);
            split2(accS[2 * kt + 1][2], accS[2 * kt + 1][3], pah[3], pal[3]);
#pragma unroll
            for (int n2 = 0; n2 < 4; n2++) {
                uint32_t eo = (uint32_t)((kt * 16 + vRow) * LKV + n2 * 16 + vCol) * 2u;
                uint32_t vh0, vh1, vh2, vh3, vl0, vl1, vl2, vl3;
                ldsm_x4_t(vh0, vh1, vh2, vh3, bVH + eo);
                mma_bf16(accO[n2 * 2 + 0], pah, vh0, vh1);
                mma_bf16(accO[n2 * 2 + 1], pah, vh2, vh3);
                mma_bf16(accO[n2 * 2 + 0], pal, vh0, vh1);
                mma_bf16(accO[n2 * 2 + 1], pal, vh2, vh3);
                ldsm_x4_t(vl0, vl1, vl2, vl3, bVL + eo);
                mma_bf16(accO[n2 * 2 + 0], pah, vl0, vl1);
                mma_bf16(accO[n2 * 2 + 1], pah, vl2, vl3);
            }
        }
        __syncthreads();
    }

    float inv0 = 1.0f / lrow[0];
    float inv1 = 1.0f / lrow[1];
    int t0 = q0 + warp * 16 + (lane >> 2);
    int t1 = t0 + 8;
#pragma unroll
    for (int nt = 0; nt < 8; nt++) {
        int hd = nt * 8 + 2 * (lane & 3);
        size_t i0 = ((size_t)b * TSEQ + t0) * INNER + h * HDIM + hd;
        size_t i1 = ((size_t)b * TSEQ + t1) * INNER + h * HDIM + hd;
        uint32_t hv, lv;
        split2(accO[nt][0] * inv0, accO[nt][1] * inv0, hv, lv);
        *reinterpret_cast<uint32_t*>(g_ATTH + i0) = hv;
        *reinterpret_cast<uint32_t*>(g_ATTL + i0) = lv;
        split2(accO[nt][2] * inv1, accO[nt][3] * inv1, hv, lv);
        *reinterpret_cast<uint32_t*>(g_ATTH + i1) = hv;
        *reinterpret_cast<uint32_t*>(g_ATTL + i1) = lv;
    }
}

// ===========================================================================
extern "C" void kernel_launch(void* const* d_in, const int* in_sizes, int n_in,
                              void* d_out, int out_size)
{
    const float* x     = (const float*)d_in[0];
    const float* qkv_w = (const float*)d_in[1];
    const float* qkv_b = (const float*)d_in[2];
    const float* out_w = (const float*)d_in[3];
    const float* out_b = (const float*)d_in[4];
    float* out = (float*)d_out;

    static __nv_bfloat16 *xH, *xL, *w1H, *w1L, *w2H, *w2L, *attH, *attL;
    static int configured = 0;
    if (!configured) {
        cudaFuncSetAttribute(gemm_bf16_kernel,
                             cudaFuncAttributeMaxDynamicSharedMemorySize, GEMM_SMEM);
        cudaFuncSetAttribute(attn_mma_kernel,
                             cudaFuncAttributeMaxDynamicSharedMemorySize, ATT2_SMEM);
        cudaGetSymbolAddress((void**)&xH,  g_xH);
        cudaGetSymbolAddress((void**)&xL,  g_xL);
        cudaGetSymbolAddress((void**)&w1H, g_w1H);
        cudaGetSymbolAddress((void**)&w1L, g_w1L);
        cudaGetSymbolAddress((void**)&w2H, g_w2H);
        cudaGetSymbolAddress((void**)&w2L, g_w2L);
        cudaGetSymbolAddress((void**)&attH, g_ATTH);
        cudaGetSymbolAddress((void**)&attL, g_ATTL);
        configured = 1;
    }

    split_kernel<<<(MROWS * KDIM / 4 + 255) / 256, 256>>>(x, xH, xL, MROWS * KDIM / 4);
    split_kernel<<<(E3 * KDIM / 4 + 255) / 256, 256>>>(qkv_w, w1H, w1L, E3 * KDIM / 4);
    split_kernel<<<(DMODEL * INNER / 4 + 255) / 256, 256>>>(out_w, w2H, w2L,
                                                            DMODEL * INNER / 4);

    dim3 g1(E3 / 128, MROWS / 128);
    gemm_bf16_kernel<<<g1, 256, GEMM_SMEM>>>(xH, xL, w1H, w1L, qkv_b, nullptr, 0);

    dim3 g2(TSEQ / 128, NHEAD, BSZ);
    attn_mma_kernel<<<g2, 256, ATT2_SMEM>>>();

    dim3 g3(DMODEL / 128, MROWS / 128);
    gemm_bf16_kernel<<<g3, 256, GEMM_SMEM>>>(attH, attL, w2H, w2L, out_b, out, 1);
}

// round 10
// speedup vs baseline: 1.1043x; 1.1043x over previous
#include <cuda_runtime.h>
#include <cuda_bf16.h>
#include <cstdint>

// Problem constants
#define BSZ   2
#define TSEQ  2048
#define DMODEL 1024
#define NHEAD 16
#define HDIM  64
#define INNER 1024
#define E3    3072
#define MROWS (BSZ*TSEQ)    // 4096
#define KDIM  1024

#define QKV_ELEMS ((size_t)BSZ*NHEAD*TSEQ*HDIM)   // 4M

// Split-bf16 scratch (hi + lo arrays)
__device__ __align__(256) __nv_bfloat16 g_xH[(size_t)MROWS*KDIM];
__device__ __align__(256) __nv_bfloat16 g_xL[(size_t)MROWS*KDIM];
__device__ __align__(256) __nv_bfloat16 g_w1H[(size_t)E3*KDIM];
__device__ __align__(256) __nv_bfloat16 g_w1L[(size_t)E3*KDIM];
__device__ __align__(256) __nv_bfloat16 g_w2H[(size_t)DMODEL*INNER];
__device__ __align__(256) __nv_bfloat16 g_w2L[(size_t)DMODEL*INNER];
__device__ __align__(256) __nv_bfloat16 g_QH[QKV_ELEMS];
__device__ __align__(256) __nv_bfloat16 g_QL[QKV_ELEMS];
__device__ __align__(256) __nv_bfloat16 g_KH[QKV_ELEMS];
__device__ __align__(256) __nv_bfloat16 g_KL[QKV_ELEMS];
__device__ __align__(256) __nv_bfloat16 g_VH[QKV_ELEMS];
__device__ __align__(256) __nv_bfloat16 g_VL[QKV_ELEMS];
__device__ __align__(256) __nv_bfloat16 g_ATTH[(size_t)MROWS*INNER];
__device__ __align__(256) __nv_bfloat16 g_ATTL[(size_t)MROWS*INNER];

// ===========================================================================
// Helpers
// ===========================================================================
__device__ __forceinline__ uint32_t smem_u32(const void* p) {
    uint32_t a;
    asm("{ .reg .u64 t; cvta.to.shared.u64 t, %1; cvt.u32.u64 %0, t; }"
        : "=r"(a) : "l"(p));
    return a;
}
__device__ __forceinline__ void ldsm_x4(uint32_t& r0, uint32_t& r1,
                                        uint32_t& r2, uint32_t& r3, uint32_t a) {
    asm volatile("ldmatrix.sync.aligned.m8n8.x4.shared.b16 {%0,%1,%2,%3}, [%4];"
                 : "=r"(r0), "=r"(r1), "=r"(r2), "=r"(r3) : "r"(a));
}
__device__ __forceinline__ void ldsm_x4_t(uint32_t& r0, uint32_t& r1,
                                          uint32_t& r2, uint32_t& r3, uint32_t a) {
    asm volatile("ldmatrix.sync.aligned.m8n8.x4.trans.shared.b16 {%0,%1,%2,%3}, [%4];"
                 : "=r"(r0), "=r"(r1), "=r"(r2), "=r"(r3) : "r"(a));
}
__device__ __forceinline__ void mma_bf16(float* d, const uint32_t* a,
                                         uint32_t b0, uint32_t b1) {
    asm volatile(
        "mma.sync.aligned.m16n8k16.row.col.f32.bf16.bf16.f32 "
        "{%0,%1,%2,%3}, {%4,%5,%6,%7}, {%8,%9}, {%0,%1,%2,%3};"
        : "+f"(d[0]), "+f"(d[1]), "+f"(d[2]), "+f"(d[3])
        : "r"(a[0]), "r"(a[1]), "r"(a[2]), "r"(a[3]), "r"(b0), "r"(b1));
}
__device__ __forceinline__ float ex2f(float x) {
    float r;
    asm("ex2.approx.f32 %0, %1;" : "=f"(r) : "f"(x));
    return r;
}
__device__ __forceinline__ void split2(float a, float b, uint32_t& hi, uint32_t& lo) {
    __nv_bfloat162 h = __floats2bfloat162_rn(a, b);
    hi = *reinterpret_cast<uint32_t*>(&h);
    __nv_bfloat162 l = __floats2bfloat162_rn(a - __bfloat162float(h.x),
                                             b - __bfloat162float(h.y));
    lo = *reinterpret_cast<uint32_t*>(&l);
}
__device__ __forceinline__ void cvt_split4(float4 v, uint2& hi, uint2& lo) {
    split2(v.x, v.y, hi.x, lo.x);
    split2(v.z, v.w, hi.y, lo.y);
}
#define CP_ASYNC16(dst, src) \
    asm volatile("cp.async.cg.shared.global [%0], [%1], 16;" :: \
                 "r"(dst), "l"(src) : "memory")
#define CP_COMMIT() asm volatile("cp.async.commit_group;" ::: "memory")
#define CP_WAIT(N)  asm volatile("cp.async.wait_group %0;" :: "n"(N) : "memory")

// ===========================================================================
// Prep: fp32 -> split bf16 (hi, lo)
// ===========================================================================
__global__ __launch_bounds__(256) void split_kernel(
    const float* __restrict__ src, __nv_bfloat16* __restrict__ hi,
    __nv_bfloat16* __restrict__ lo, int n4)
{
    int i = blockIdx.x * 256 + threadIdx.x;
    if (i < n4) {
        float4 v = reinterpret_cast<const float4*>(src)[i];
        uint2 h, l;
        cvt_split4(v, h, l);
        reinterpret_cast<uint2*>(hi)[i] = h;
        reinterpret_cast<uint2*>(lo)[i] = l;
    }
}

// ===========================================================================
// Split-bf16 tensor-core GEMM.
// 256 threads (8 warps, 4x2), CTA tile 128x128, warp tile 32x64.
// K-chunk 32, 2-stage cp.async, __launch_bounds__(256,2) -> 2 CTAs/SM.
// Inner loop streams B fragments (one j-subtile at a time) to cap regs <=128.
// mode 0: scatter + re-split into g_{Q,K,V}{H,L} ([b][h][t][d])
// mode 1: write fp32 C[m*DMODEL+n] + bias
// ===========================================================================
#define GST 40960u                    // bytes/stage: 4 arrays x 128 rows x 80B
#define GSTAGES 2
#define GEMM_SMEM (GSTAGES*GST)       // 81920 -> 2 CTAs/SM
#define GNCH (KDIM/32)                // 32 chunks

__global__ __launch_bounds__(256, 2) void gemm_bf16_kernel(
    const __nv_bfloat16* __restrict__ Ah, const __nv_bfloat16* __restrict__ Al,
    const __nv_bfloat16* __restrict__ Bh, const __nv_bfloat16* __restrict__ Bl,
    const float* __restrict__ bias, float* __restrict__ C, int mode)
{
    extern __shared__ char smem[];
    const uint32_t sb = smem_u32(smem);
    const int tid  = threadIdx.x;
    const int lane = tid & 31;
    const int warp = tid >> 5;        // 0..7
    const int wm = warp & 3;          // m: 32*wm
    const int wn = warp >> 2;         // n: 64*wn
    const int n0 = blockIdx.x * 128;
    const int m0 = blockIdx.y * 128;

    // copy role: arr 0=Ah 1=Al 2=Bh 3=Bl ; 64 threads per array, 2 rows each
    const int cp_arr = tid >> 6;
    const int cp_r0  = (tid & 63) * 2;
    const __nv_bfloat16* srcp =
        (cp_arr == 0) ? Ah : (cp_arr == 1) ? Al : (cp_arr == 2) ? Bh : Bl;
    srcp += (size_t)((cp_arr < 2 ? m0 : n0) + cp_r0) * KDIM;
    const uint32_t dst0 = sb + (uint32_t)cp_arr * 10240u + (uint32_t)cp_r0 * 80u;

    auto issue_chunk = [&](int ch, int stage) {
        uint32_t d = dst0 + (uint32_t)stage * GST;
        const __nv_bfloat16* s = srcp + ch * 32;
#pragma unroll
        for (int rr = 0; rr < 2; rr++) {
#pragma unroll
            for (int c = 0; c < 4; c++)
                CP_ASYNC16(d + rr * 80u + c * 16u, s + (size_t)rr * KDIM + c * 8);
        }
        CP_COMMIT();
    };

    float acc[2][8][4];
#pragma unroll
    for (int i = 0; i < 2; i++)
#pragma unroll
        for (int f = 0; f < 8; f++)
#pragma unroll
            for (int q = 0; q < 4; q++) acc[i][f][q] = 0.f;

    const int aRowB = wm * 32 + (lane & 15);
    const int aColB = (lane >> 4) * 8;
    const int bRowB = wn * 64 + ((lane >> 4) * 8) + (lane & 7);
    const int bColB = ((lane >> 3) & 1) * 8;

    issue_chunk(0, 0);

    for (int ch = 0; ch < GNCH; ch++) {
        const int st = ch & 1;
        if (ch + 1 < GNCH) {
            issue_chunk(ch + 1, st ^ 1);
            CP_WAIT(1);
        } else {
            CP_WAIT(0);
        }
        __syncthreads();

        const uint32_t base = sb + (uint32_t)st * GST;
        const uint32_t bAH = base, bAL = base + 10240u;
        const uint32_t bBH = base + 20480u, bBL = base + 30720u;

#pragma unroll
        for (int ks = 0; ks < 32; ks += 16) {
            // A fragments (hi + lo): 16 regs live
            uint32_t ah[2][4], al[2][4];
#pragma unroll
            for (int i = 0; i < 2; i++) {
                uint32_t eo = (uint32_t)((aRowB + i * 16) * 80 + (ks + aColB) * 2);
                ldsm_x4(ah[i][0], ah[i][1], ah[i][2], ah[i][3], bAH + eo);
                ldsm_x4(al[i][0], al[i][1], al[i][2], al[i][3], bAL + eo);
            }
            // Stream B subtiles: bh/bl for one j at a time (8 regs live)
#pragma unroll
            for (int j = 0; j < 4; j++) {
                uint32_t eo = (uint32_t)((bRowB + j * 16) * 80 + (ks + bColB) * 2);
                uint32_t bh0, bh1, bh2, bh3, bl0, bl1, bl2, bl3;
                ldsm_x4(bh0, bh1, bh2, bh3, bBH + eo);
                ldsm_x4(bl0, bl1, bl2, bl3, bBL + eo);
#pragma unroll
                for (int i = 0; i < 2; i++) {
                    mma_bf16(acc[i][j * 2 + 0], ah[i], bh0, bh1);
                    mma_bf16(acc[i][j * 2 + 1], ah[i], bh2, bh3);
                    mma_bf16(acc[i][j * 2 + 0], ah[i], bl0, bl1);
                    mma_bf16(acc[i][j * 2 + 1], ah[i], bl2, bl3);
                    mma_bf16(acc[i][j * 2 + 0], al[i], bh0, bh1);
                    mma_bf16(acc[i][j * 2 + 1], al[i], bh2, bh3);
                }
            }
        }
        __syncthreads();
    }

    // Epilogue
#pragma unroll
    for (int i = 0; i < 2; i++) {
#pragma unroll
        for (int f = 0; f < 8; f++) {
            int row = m0 + wm * 32 + i * 16 + (lane >> 2);
            int col = n0 + wn * 64 + f * 8 + (lane & 3) * 2;
            float b0 = bias[col], b1 = bias[col + 1];
            float p00 = acc[i][f][0] + b0, p01 = acc[i][f][1] + b1;
            float p10 = acc[i][f][2] + b0, p11 = acc[i][f][3] + b1;
            if (mode == 0) {
                int which = col >> 10, h = (col >> 6) & (NHEAD - 1), d = col & (HDIM - 1);
                __nv_bfloat16* dh = (which == 0) ? g_QH : (which == 1) ? g_KH : g_VH;
                __nv_bfloat16* dl = (which == 0) ? g_QL : (which == 1) ? g_KL : g_VL;
#pragma unroll
                for (int rr = 0; rr < 2; rr++) {
                    int r = row + rr * 8;
                    int bb = r >> 11, tt = r & (TSEQ - 1);
                    size_t idx = (((size_t)(bb * NHEAD + h)) * TSEQ + tt) * HDIM + d;
                    uint32_t hv, lv;
                    split2(rr ? p10 : p00, rr ? p11 : p01, hv, lv);
                    *reinterpret_cast<uint32_t*>(dh + idx) = hv;
                    *reinterpret_cast<uint32_t*>(dl + idx) = lv;
                }
            } else {
                float2 v0 = {p00, p01}, v1 = {p10, p11};
                *reinterpret_cast<float2*>(&C[(size_t)row * DMODEL + col]) = v0;
                *reinterpret_cast<float2*>(&C[(size_t)(row + 8) * DMODEL + col]) = v1;
            }
        }
    }
}

// ===========================================================================
// Tensor-core flash attention, split-bf16 inputs, anti-causal (keep j >= i).
// 256 threads, 8 warps x 16 query rows, key tiles of 64, cp.async KV pipeline.
// (unchanged — passed)
// ===========================================================================
#define LKV 72
#define AQH 0
#define AQL (128*LKV*2)               // 18432
#define AKV0 (2*128*LKV*2)            // 36864
#define KVST (4*64*LKV*2)             // 36864 per stage (KH,KL,VH,VL)
#define ATT2_SMEM (AKV0 + 2*KVST)     // 110592

__global__ __launch_bounds__(256) void attn_mma_kernel()
{
    extern __shared__ char smem[];
    const uint32_t sb = smem_u32(smem);
    const int tid  = threadIdx.x;
    const int lane = tid & 31;
    const int warp = tid >> 5;
    const int q0 = blockIdx.x * 128;
    const int h  = blockIdx.y;
    const int b  = blockIdx.z;
    const size_t head_off = (size_t)(b * NHEAD + h) * TSEQ * HDIM;

    const float QSCALE = 0.18033688011112042f;   // 0.125 * log2(e)

    auto issue_kv = [&](int stage, int j0) {
        uint32_t kvb = sb + AKV0 + (uint32_t)stage * KVST;
#pragma unroll
        for (int it = 0; it < 8; it++) {
            int idx = tid + it * 256;
            int arr = idx >> 9;
            int rem = idx & 511;
            int r = rem >> 3, c8 = rem & 7;
            const __nv_bfloat16* s =
                (arr == 0) ? g_KH : (arr == 1) ? g_KL : (arr == 2) ? g_VH : g_VL;
            s += head_off + (size_t)(j0 + r) * HDIM + c8 * 8;
            uint32_t d = kvb + (uint32_t)arr * 9216u + (uint32_t)(r * 144 + c8 * 16);
            CP_ASYNC16(d, s);
        }
        CP_COMMIT();
    };
    issue_kv(0, q0);

#pragma unroll
    for (int it = 0; it < 4; it++) {
        int idx = tid + it * 256;
        int r = idx >> 3, c8 = idx & 7;
        size_t goff = head_off + (size_t)(q0 + r) * HDIM + c8 * 8;
        uint32_t soff = (uint32_t)(r * 144 + c8 * 16);
        *reinterpret_cast<uint4*>(smem + AQH + soff) =
            *reinterpret_cast<const uint4*>(g_QH + goff);
        *reinterpret_cast<uint4*>(smem + AQL + soff) =
            *reinterpret_cast<const uint4*>(g_QL + goff);
    }
    __syncthreads();

    uint32_t qh[4][4], ql[4][4];
    {
        const int aRow = warp * 16 + (lane & 15);
        const int aCol = (lane >> 4) * 8;
#pragma unroll
        for (int kt = 0; kt < 4; kt++) {
            uint32_t eo = (uint32_t)(aRow * LKV + kt * 16 + aCol) * 2u;
            ldsm_x4(qh[kt][0], qh[kt][1], qh[kt][2], qh[kt][3], sb + AQH + eo);
            ldsm_x4(ql[kt][0], ql[kt][1], ql[kt][2], ql[kt][3], sb + AQL + eo);
        }
    }

    float accO[8][4];
#pragma unroll
    for (int n = 0; n < 8; n++)
#pragma unroll
        for (int c = 0; c < 4; c++) accO[n][c] = 0.f;
    float mrow[2] = {-1e30f, -1e30f};
    float lrow[2] = {0.f, 0.f};

    const int ntiles = (TSEQ - q0) / 64;

    for (int tc = 0; tc < ntiles; tc++) {
        const int j0 = q0 + tc * 64;
        const int st = tc & 1;
        if (tc + 1 < ntiles) {
            issue_kv(st ^ 1, j0 + 64);
            CP_WAIT(1);
        } else {
            CP_WAIT(0);
        }
        __syncthreads();

        const uint32_t kvb = sb + AKV0 + (uint32_t)st * KVST;
        const uint32_t bKH = kvb, bKL = kvb + 9216u;
        const uint32_t bVH = kvb + 18432u, bVL = kvb + 27648u;

        float accS[8][4];
#pragma unroll
        for (int n = 0; n < 8; n++)
#pragma unroll
            for (int c = 0; c < 4; c++) accS[n][c] = 0.f;

        const int kRow = ((lane >> 4) * 8) + (lane & 7);
        const int kCol = ((lane >> 3) & 1) * 8;
#pragma unroll
        for (int kt = 0; kt < 4; kt++) {
#pragma unroll
            for (int j2 = 0; j2 < 4; j2++) {
                uint32_t eo = (uint32_t)((j2 * 16 + kRow) * LKV + kt * 16 + kCol) * 2u;
                uint32_t kh0, kh1, kh2, kh3, kl0, kl1, kl2, kl3;
                ldsm_x4(kh0, kh1, kh2, kh3, bKH + eo);
                mma_bf16(accS[j2 * 2 + 0], qh[kt], kh0, kh1);
                mma_bf16(accS[j2 * 2 + 1], qh[kt], kh2, kh3);
                mma_bf16(accS[j2 * 2 + 0], ql[kt], kh0, kh1);
                mma_bf16(accS[j2 * 2 + 1], ql[kt], kh2, kh3);
                ldsm_x4(kl0, kl1, kl2, kl3, bKL + eo);
                mma_bf16(accS[j2 * 2 + 0], qh[kt], kl0, kl1);
                mma_bf16(accS[j2 * 2 + 1], qh[kt], kl2, kl3);
            }
        }

#pragma unroll
        for (int n = 0; n < 8; n++)
#pragma unroll
            for (int c = 0; c < 4; c++) accS[n][c] *= QSCALE;

        if (j0 - q0 < 128) {
            int rq = q0 + warp * 16 + (lane >> 2);
#pragma unroll
            for (int nt = 0; nt < 8; nt++) {
                int cb = j0 + nt * 8 + 2 * (lane & 3);
                if (cb     < rq)     accS[nt][0] = -1e30f;
                if (cb + 1 < rq)     accS[nt][1] = -1e30f;
                if (cb     < rq + 8) accS[nt][2] = -1e30f;
                if (cb + 1 < rq + 8) accS[nt][3] = -1e30f;
            }
        }

#pragma unroll
        for (int r = 0; r < 2; r++) {
            float tm = -1e30f;
#pragma unroll
            for (int nt = 0; nt < 8; nt++)
                tm = fmaxf(tm, fmaxf(accS[nt][r * 2], accS[nt][r * 2 + 1]));
            tm = fmaxf(tm, __shfl_xor_sync(0xffffffffu, tm, 1));
            tm = fmaxf(tm, __shfl_xor_sync(0xffffffffu, tm, 2));
            float mnew = fmaxf(mrow[r], tm);
            float alpha = ex2f(mrow[r] - mnew);
            mrow[r] = mnew;
            float rs = 0.f;
#pragma unroll
            for (int nt = 0; nt < 8; nt++) {
                float p0 = ex2f(accS[nt][r * 2]     - mnew);
                float p1 = ex2f(accS[nt][r * 2 + 1] - mnew);
                accS[nt][r * 2] = p0;
                accS[nt][r * 2 + 1] = p1;
                rs += p0 + p1;
            }
            rs += __shfl_xor_sync(0xffffffffu, rs, 1);
            rs += __shfl_xor_sync(0xffffffffu, rs, 2);
            lrow[r] = lrow[r] * alpha + rs;
#pragma unroll
            for (int nt = 0; nt < 8; nt++) {
                accO[nt][r * 2]     *= alpha;
                accO[nt][r * 2 + 1] *= alpha;
            }
        }

        const int vRow = lane & 15;
        const int vCol = (lane >> 4) * 8;
#pragma unroll
        for (int kt = 0; kt < 4; kt++) {
            uint32_t pah[4], pal[4];
            split2(accS[2 * kt][0],     accS[2 * kt][1],     pah[0], pal[0]);
            split2(accS[2 * kt][2],     accS[2 * kt][3],     pah[1], pal[1]);
            split2(accS[2 * kt + 1][0], accS[2 * kt + 1][1], pah[2], pal[2]);
            split2(accS[2 * kt + 1][2], accS[2 * kt + 1][3], pah[3], pal[3]);
#pragma unroll
            for (int n2 = 0; n2 < 4; n2++) {
                uint32_t eo = (uint32_t)((kt * 16 + vRow) * LKV + n2 * 16 + vCol) * 2u;
                uint32_t vh0, vh1, vh2, vh3, vl0, vl1, vl2, vl3;
                ldsm_x4_t(vh0, vh1, vh2, vh3, bVH + eo);
                mma_bf16(accO[n2 * 2 + 0], pah, vh0, vh1);
                mma_bf16(accO[n2 * 2 + 1], pah, vh2, vh3);
                mma_bf16(accO[n2 * 2 + 0], pal, vh0, vh1);
                mma_bf16(accO[n2 * 2 + 1], pal, vh2, vh3);
                ldsm_x4_t(vl0, vl1, vl2, vl3, bVL + eo);
                mma_bf16(accO[n2 * 2 + 0], pah, vl0, vl1);
                mma_bf16(accO[n2 * 2 + 1], pah, vl2, vl3);
            }
        }
        __syncthreads();
    }

    float inv0 = 1.0f / lrow[0];
    float inv1 = 1.0f / lrow[1];
    int t0 = q0 + warp * 16 + (lane >> 2);
    int t1 = t0 + 8;
#pragma unroll
    for (int nt = 0; nt < 8; nt++) {
        int hd = nt * 8 + 2 * (lane & 3);
        size_t i0 = ((size_t)b * TSEQ + t0) * INNER + h * HDIM + hd;
        size_t i1 = ((size_t)b * TSEQ + t1) * INNER + h * HDIM + hd;
        uint32_t hv, lv;
        split2(accO[nt][0] * inv0, accO[nt][1] * inv0, hv, lv);
        *reinterpret_cast<uint32_t*>(g_ATTH + i0) = hv;
        *reinterpret_cast<uint32_t*>(g_ATTL + i0) = lv;
        split2(accO[nt][2] * inv1, accO[nt][3] * inv1, hv, lv);
        *reinterpret_cast<uint32_t*>(g_ATTH + i1) = hv;
        *reinterpret_cast<uint32_t*>(g_ATTL + i1) = lv;
    }
}

// ===========================================================================
extern "C" void kernel_launch(void* const* d_in, const int* in_sizes, int n_in,
                              void* d_out, int out_size)
{
    const float* x     = (const float*)d_in[0];
    const float* qkv_w = (const float*)d_in[1];
    const float* qkv_b = (const float*)d_in[2];
    const float* out_w = (const float*)d_in[3];
    const float* out_b = (const float*)d_in[4];
    float* out = (float*)d_out;

    static __nv_bfloat16 *xH, *xL, *w1H, *w1L, *w2H, *w2L, *attH, *attL;
    static int configured = 0;
    if (!configured) {
        cudaFuncSetAttribute(gemm_bf16_kernel,
                             cudaFuncAttributeMaxDynamicSharedMemorySize, GEMM_SMEM);
        cudaFuncSetAttribute(attn_mma_kernel,
                             cudaFuncAttributeMaxDynamicSharedMemorySize, ATT2_SMEM);
        cudaGetSymbolAddress((void**)&xH,  g_xH);
        cudaGetSymbolAddress((void**)&xL,  g_xL);
        cudaGetSymbolAddress((void**)&w1H, g_w1H);
        cudaGetSymbolAddress((void**)&w1L, g_w1L);
        cudaGetSymbolAddress((void**)&w2H, g_w2H);
        cudaGetSymbolAddress((void**)&w2L, g_w2L);
        cudaGetSymbolAddress((void**)&attH, g_ATTH);
        cudaGetSymbolAddress((void**)&attL, g_ATTL);
        configured = 1;
    }

    split_kernel<<<(MROWS * KDIM / 4 + 255) / 256, 256>>>(x, xH, xL, MROWS * KDIM / 4);
    split_kernel<<<(E3 * KDIM / 4 + 255) / 256, 256>>>(qkv_w, w1H, w1L, E3 * KDIM / 4);
    split_kernel<<<(DMODEL * INNER / 4 + 255) / 256, 256>>>(out_w, w2H, w2L,
                                                            DMODEL * INNER / 4);

    dim3 g1(E3 / 128, MROWS / 128);
    gemm_bf16_kernel<<<g1, 256, GEMM_SMEM>>>(xH, xL, w1H, w1L, qkv_b, nullptr, 0);

    dim3 g2(TSEQ / 128, NHEAD, BSZ);
    attn_mma_kernel<<<g2, 256, ATT2_SMEM>>>();

    dim3 g3(DMODEL / 128, MROWS / 128);
    gemm_bf16_kernel<<<g3, 256, GEMM_SMEM>>>(attH, attL, w2H, w2L, out_b, out, 1);
}